// round 1
// baseline (speedup 1.0000x reference)
#include <cuda_runtime.h>
#include <cuda_bf16.h>
#include <cstdint>

// Problem constants (from reference)
#define B_  8
#define L_  2048
#define P_  576
#define V_  32000
#define D_  2560
#define T_  (L_ - 1 + P_)      // 2623
#define IGNORE_INDEX_ (-100)

// One block per output row (b, t). Copies D floats via float4 (640 per row).
// Thread 0 additionally writes the scalar tails (labels / mask / position_ids),
// which live after the embedding block in the concatenated float32 output.
__global__ void __launch_bounds__(256)
splice_kernel(const float* __restrict__ embed_table,     // [V, D]
              const float* __restrict__ image_features,  // [B, P, D]
              const int*   __restrict__ input_ids,       // [B, L]
              const int*   __restrict__ labels,          // [B, L]
              const int*   __restrict__ img_pos,         // [B]
              float* __restrict__ out)
{
    const int row = blockIdx.x;           // 0 .. B*T-1
    const int b = row / T_;
    const int t = row - b * T_;

    const int pos = img_pos[b];
    const bool is_img = (t >= pos) && (t < pos + P_);

    // token index (clipped)
    int tok_idx = (t < pos) ? t : (t - P_ + 1);
    tok_idx = max(0, min(tok_idx, L_ - 1));

    const float4* __restrict__ src;
    if (is_img) {
        int img_idx = max(0, min(t - pos, P_ - 1));
        src = reinterpret_cast<const float4*>(
            image_features + ((long long)b * P_ + img_idx) * D_);
    } else {
        int tok = input_ids[b * L_ + tok_idx];
        src = reinterpret_cast<const float4*>(
            embed_table + (long long)tok * D_);
    }

    float4* __restrict__ dst =
        reinterpret_cast<float4*>(out + (long long)row * D_);

    #pragma unroll 4
    for (int i = threadIdx.x; i < D_ / 4; i += blockDim.x) {
        dst[i] = src[i];
    }

    if (threadIdx.x == 0) {
        float* tails = out + (long long)B_ * T_ * D_;
        // new_labels
        tails[row] = is_img ? (float)IGNORE_INDEX_
                            : (float)labels[b * L_ + tok_idx];
        // attention_mask (all true)
        tails[(long long)B_ * T_ + row] = 1.0f;
        // position_ids (iota over T)
        tails[2LL * B_ * T_ + row] = (float)t;
    }
}

extern "C" void kernel_launch(void* const* d_in, const int* in_sizes, int n_in,
                              void* d_out, int out_size)
{
    const float* embed_table    = (const float*)d_in[0];
    const float* image_features = (const float*)d_in[1];
    const int*   input_ids      = (const int*)  d_in[2];
    const int*   labels         = (const int*)  d_in[3];
    const int*   img_pos        = (const int*)  d_in[4];
    float* out = (float*)d_out;

    const int n_rows = B_ * T_;   // 20984
    splice_kernel<<<n_rows, 256>>>(embed_table, image_features,
                                   input_ids, labels, img_pos, out);
}

// round 2
// speedup vs baseline: 1.0816x; 1.0816x over previous
#include <cuda_runtime.h>
#include <cuda_bf16.h>
#include <cstdint>

// Problem constants (from reference)
#define B_  8
#define L_  2048
#define P_  576
#define V_  32000
#define D_  2560
#define T_  (L_ - 1 + P_)      // 2623
#define IGNORE_INDEX_ (-100)

// One block per output row (b, t). 640 float4 per row, 256 threads:
// each thread does 2 unconditional + (tid<128 ? 1 : 0) predicated copies,
// loads front-batched before stores for max MLP.
//
// Cache policy: output is write-once streaming -> __stcs (evict-first),
// image_features read-once -> __ldcs, embed_table rows are the reused
// working set (~127MB ~ L2 capacity) -> default cached __ldg.
__global__ void __launch_bounds__(256)
splice_kernel(const float* __restrict__ embed_table,     // [V, D]
              const float* __restrict__ image_features,  // [B, P, D]
              const int*   __restrict__ input_ids,       // [B, L]
              const int*   __restrict__ labels,          // [B, L]
              const int*   __restrict__ img_pos,         // [B]
              float* __restrict__ out)
{
    const int row = blockIdx.x;           // 0 .. B*T-1
    const int b = row / T_;
    const int t = row - b * T_;

    const int pos = img_pos[b];
    const bool is_img = (t >= pos) && (t < pos + P_);

    int tok_idx = (t < pos) ? t : (t - P_ + 1);
    tok_idx = max(0, min(tok_idx, L_ - 1));

    float4* __restrict__ dst =
        reinterpret_cast<float4*>(out + (long long)row * D_);

    const int i0 = threadIdx.x;           // 0..255
    const int i1 = i0 + 256;              // 256..511
    const int i2 = i0 + 512;              // 512..639 (i0 < 128 only)
    const bool has2 = (i0 < 128);

    if (is_img) {
        const int img_idx = max(0, min(t - pos, P_ - 1));
        const float4* __restrict__ src = reinterpret_cast<const float4*>(
            image_features + ((long long)b * P_ + img_idx) * D_);
        // read-once stream: evict-first loads
        float4 a = __ldcs(src + i0);
        float4 c = __ldcs(src + i1);
        float4 e;
        if (has2) e = __ldcs(src + i2);
        __stcs(dst + i0, a);
        __stcs(dst + i1, c);
        if (has2) __stcs(dst + i2, e);
    } else {
        const int tok = input_ids[b * L_ + tok_idx];
        const float4* __restrict__ src = reinterpret_cast<const float4*>(
            embed_table + (long long)tok * D_);
        // reused working set: keep cached in L2
        float4 a = __ldg(src + i0);
        float4 c = __ldg(src + i1);
        float4 e;
        if (has2) e = __ldg(src + i2);
        __stcs(dst + i0, a);
        __stcs(dst + i1, c);
        if (has2) __stcs(dst + i2, e);
    }

    if (threadIdx.x == 0) {
        float* tails = out + (long long)B_ * T_ * D_;
        // new_labels
        tails[row] = is_img ? (float)IGNORE_INDEX_
                            : (float)labels[b * L_ + tok_idx];
        // attention_mask (all true)
        tails[(long long)B_ * T_ + row] = 1.0f;
        // position_ids (iota over T)
        tails[2LL * B_ * T_ + row] = (float)t;
    }
}

extern "C" void kernel_launch(void* const* d_in, const int* in_sizes, int n_in,
                              void* d_out, int out_size)
{
    const float* embed_table    = (const float*)d_in[0];
    const float* image_features = (const float*)d_in[1];
    const int*   input_ids      = (const int*)  d_in[2];
    const int*   labels         = (const int*)  d_in[3];
    const int*   img_pos        = (const int*)  d_in[4];
    float* out = (float*)d_out;

    const int n_rows = B_ * T_;   // 20984
    splice_kernel<<<n_rows, 256>>>(embed_table, image_features,
                                   input_ids, labels, img_pos, out);
}